// round 13
// baseline (speedup 1.0000x reference)
#include <cuda_runtime.h>
#include <cuda_fp16.h>
#include <stdint.h>
#include <math.h>

#define NN 8192
#define INF_ 256
#define OUTF 128
#define BHC 136     // g_Bh cols: 0-127 = D5*Wh, 128 = D5, 129-135 = 0

// ------------------------------ scratch ------------------------------------
__device__ float g_Wh[NN * OUTF];                 // 4 MB
__device__ __align__(16) __half g_Bh[NN * BHC];   // 2.2 MB
__device__ float g_R[NN];                         // exp(0.8*src)
__device__ __half g_Qh[NN];                       // f16(exp(0.8*dst))
__device__ float g_D5[NN];                        // exp(0.2*dst)
__device__ float g_pnum[2 * NN * OUTF];           // split-K partial numerators
__device__ float g_pden[2 * NN];                  // split-K partial denominators

// ------------------------------ helpers ------------------------------------
__device__ __forceinline__ uint32_t smem_u32(const void* p) {
    return (uint32_t)__cvta_generic_to_shared(p);
}
__device__ __forceinline__ void ldsm_x4(uint32_t* r, uint32_t addr) {
    asm volatile("ldmatrix.sync.aligned.m8n8.x4.shared.b16 {%0,%1,%2,%3}, [%4];"
        : "=r"(r[0]), "=r"(r[1]), "=r"(r[2]), "=r"(r[3]) : "r"(addr));
}
__device__ __forceinline__ void ldsm_x4_t(uint32_t* r, uint32_t addr) {
    asm volatile("ldmatrix.sync.aligned.m8n8.x4.trans.shared.b16 {%0,%1,%2,%3}, [%4];"
        : "=r"(r[0]), "=r"(r[1]), "=r"(r[2]), "=r"(r[3]) : "r"(addr));
}
__device__ __forceinline__ void mma_f16(float* d, const uint32_t* a, const uint32_t* b) {
    asm volatile(
        "mma.sync.aligned.m16n8k16.row.col.f32.f16.f16.f32 "
        "{%0,%1,%2,%3}, {%4,%5,%6,%7}, {%8,%9}, {%0,%1,%2,%3};"
        : "+f"(d[0]), "+f"(d[1]), "+f"(d[2]), "+f"(d[3])
        : "r"(a[0]), "r"(a[1]), "r"(a[2]), "r"(a[3]), "r"(b[0]), "r"(b[1]));
}
__device__ __forceinline__ uint32_t pack_h2(float lo, float hi) {
    __half2 h = __float22half2_rn(make_float2(lo, hi));
    return *(uint32_t*)&h;
}
__device__ __forceinline__ void cp_async16(uint32_t dst, const void* src) {
    asm volatile("cp.async.cg.shared.global [%0], [%1], 16;" :: "r"(dst), "l"(src));
}
#define CP_COMMIT()  asm volatile("cp.async.commit_group;" ::: "memory")
#define CP_WAIT1()   asm volatile("cp.async.wait_group 1;" ::: "memory")

// ---------------------------------------------------------------------------
// Kernel A: Wh = h @ W   (fp32)
// ---------------------------------------------------------------------------
__global__ __launch_bounds__(256) void wh_kernel(const float* __restrict__ h,
                                                 const float* __restrict__ W) {
    __shared__ float hs[64 * 68];
    __shared__ float Ws[64 * 128];
    const int tid = threadIdx.x;
    const int ty = tid >> 4, tx = tid & 15;
    const int rowbase = blockIdx.x * 64;
    float acc[4][8];
#pragma unroll
    for (int i = 0; i < 4; i++)
#pragma unroll
        for (int c = 0; c < 8; c++) acc[i][c] = 0.f;
    const float4* h4 = (const float4*)h;
    const float4* W4 = (const float4*)W;
    for (int kt = 0; kt < INF_; kt += 64) {
        __syncthreads();
#pragma unroll
        for (int s = 0; s < 4; s++) {
            int f4 = tid + s * 256;
            int r = f4 >> 4, c4 = f4 & 15;
            float4 v = h4[(size_t)(rowbase + r) * 64 + (kt >> 2) + c4];
            *(float4*)&hs[r * 68 + c4 * 4] = v;
        }
#pragma unroll
        for (int s = 0; s < 8; s++) {
            int f4 = tid + s * 256;
            ((float4*)Ws)[f4] = W4[kt * 32 + f4];
        }
        __syncthreads();
#pragma unroll 8
        for (int k = 0; k < 64; k++) {
            float hv[4];
#pragma unroll
            for (int i = 0; i < 4; i++) hv[i] = hs[(ty * 4 + i) * 68 + k];
            float4 w0 = *(const float4*)&Ws[k * 128 + tx * 4];
            float4 w1 = *(const float4*)&Ws[k * 128 + 64 + tx * 4];
#pragma unroll
            for (int i = 0; i < 4; i++) {
                acc[i][0] += hv[i] * w0.x; acc[i][1] += hv[i] * w0.y;
                acc[i][2] += hv[i] * w0.z; acc[i][3] += hv[i] * w0.w;
                acc[i][4] += hv[i] * w1.x; acc[i][5] += hv[i] * w1.y;
                acc[i][6] += hv[i] * w1.z; acc[i][7] += hv[i] * w1.w;
            }
        }
    }
#pragma unroll
    for (int i = 0; i < 4; i++) {
        int r = rowbase + ty * 4 + i;
        ((float4*)g_Wh)[(size_t)r * 32 + tx] = make_float4(acc[i][0], acc[i][1], acc[i][2], acc[i][3]);
        ((float4*)g_Wh)[(size_t)r * 32 + 16 + tx] = make_float4(acc[i][4], acc[i][5], acc[i][6], acc[i][7]);
    }
}

// ---------------------------------------------------------------------------
// Kernel B: per-node R = exp(0.8*src), Qh = f16(exp(0.8*dst)), D5 = exp(0.2*dst)
// ---------------------------------------------------------------------------
__global__ __launch_bounds__(256) void srcdst_kernel(const float* __restrict__ a) {
    const int tid = threadIdx.x;
    const int row = blockIdx.x * 64 + (tid >> 2);
    const int q = tid & 3;
    const float4* wh4 = (const float4*)(g_Wh + (size_t)row * 128) + q * 8;
    const float4* a4 = (const float4*)a;
    float s1 = 0.f, s2 = 0.f;
#pragma unroll
    for (int t = 0; t < 8; t++) {
        float4 v = wh4[t];
        float4 b1 = a4[q * 8 + t];
        float4 b2 = a4[32 + q * 8 + t];
        s1 += v.x * b1.x + v.y * b1.y + v.z * b1.z + v.w * b1.w;
        s2 += v.x * b2.x + v.y * b2.y + v.z * b2.z + v.w * b2.w;
    }
    s1 += __shfl_xor_sync(0xffffffffu, s1, 1);
    s1 += __shfl_xor_sync(0xffffffffu, s1, 2);
    s2 += __shfl_xor_sync(0xffffffffu, s2, 1);
    s2 += __shfl_xor_sync(0xffffffffu, s2, 2);
    if (q == 0) {
        g_R[row] = __expf(0.8f * s1);
        g_Qh[row] = __float2half(__expf(0.8f * s2));
        g_D5[row] = __expf(0.2f * s2);
    }
}

// ---------------------------------------------------------------------------
// Kernel B2: Bh[j][0..127] = f16(D5_j*Wh[j][c]); Bh[j][128] = f16(D5_j); rest 0
// ---------------------------------------------------------------------------
__global__ __launch_bounds__(256) void bh_kernel() {
    const int idx = blockIdx.x * 256 + threadIdx.x;   // 0..262143
    const int row = idx >> 5, c4 = idx & 31;
    const float d5 = g_D5[row];
    float4 v = ((const float4*)g_Wh)[(size_t)row * 32 + c4];
    uint2 u = make_uint2(pack_h2(v.x * d5, v.y * d5), pack_h2(v.z * d5, v.w * d5));
    *(uint2*)&g_Bh[(size_t)row * BHC + c4 * 4] = u;
    if (c4 == 0) {
        *(uint2*)&g_Bh[(size_t)row * BHC + 128] = make_uint2(pack_h2(d5, 0.f), 0u);
        *(uint2*)&g_Bh[(size_t)row * BHC + 132] = make_uint2(0u, 0u);
    }
}

// ---------------------------------------------------------------------------
// Kernel C: fused masked-attention GEMM, f16 m16n8k16 + ldmatrix.
// grid = 256 (128 row-blocks of 64 x 2 K-halves), block = 256 (8 warps =
// 2m x 4n, warp tile 32x32; wn==3 also computes the den column 128).
// P_ij = adj ? max(R_i*Q_j, 1) : 0 built in f16x2 + mask-AND.
// 3-stage cp.async pipeline for B; P double-buffered; 1 barrier/tile.
// ---------------------------------------------------------------------------
#define PST 72      // P row stride in halves (144 B = 9x16B, conflict-free)
#define BST 152     // B row stride in halves (304 B = 19x16B, conflict-free)
#define PS_B (64 * PST * 2)     //  9216 B per buffer
#define BS_B (64 * BST * 2)     // 19456 B per buffer
#define OFF_BS (2 * PS_B)
#define ATTN_SMEM (OFF_BS + 3 * BS_B)   // 76800 B

__global__ __launch_bounds__(256, 2) void attn_mma_kernel(const int* __restrict__ adj) {
    extern __shared__ char sm[];

    const int tid = threadIdx.x;
    const int lane = tid & 31, wid = tid >> 5;
    const int rb = blockIdx.x >> 1, kh = blockIdx.x & 1;
    const int row0 = rb * 64, k0 = kh * 4096;

    // ---- P-build roles: rows {r0, r0+32}, j in [jq*8, jq*8+8) ----
    const int r0 = tid >> 3;
    const int jq = tid & 7;
    __half2 R2[2];
    const int4* adjp[2];
#pragma unroll
    for (int cc = 0; cc < 2; cc++) {
        R2[cc] = __float2half2_rn(g_R[row0 + r0 + 32 * cc]);
        adjp[cc] = (const int4*)(adj + (size_t)(row0 + r0 + 32 * cc) * NN + k0) + jq * 2;
    }
    const __half2 ONE2 = __float2half2_rn(1.0f);

    // ---- MMA roles: 2m x 4n ----
    const int wm = wid & 1, wn = wid >> 1;
    const int gr = lane >> 2, tg = lane & 3;
    float acc[2][4][4];
    float accD[2][4];
#pragma unroll
    for (int mt = 0; mt < 2; mt++) {
#pragma unroll
        for (int nt = 0; nt < 4; nt++)
#pragma unroll
            for (int i = 0; i < 4; i++) acc[mt][nt][i] = 0.f;
#pragma unroll
        for (int i = 0; i < 4; i++) accD[mt][i] = 0.f;
    }

    const uint32_t ps_base = smem_u32(sm);
    const uint32_t a_rel = (uint32_t)((wm * 32 + (lane & 15)) * PST + (lane >> 4) * 8) * 2;
    const uint32_t b_rel = (uint32_t)((lane & 15) * BST + wn * 32 + (lane >> 4) * 8) * 2;

    // ---- cp.async B roles ----
    const int bj0 = tid >> 4, bch = tid & 15;

    // lambda: issue B tile for j-base jb into stage st
    auto issueB = [&](int st, int jb) {
        const uint32_t dst = ps_base + OFF_BS + st * BS_B;
#pragma unroll
        for (int i = 0; i < 4; i++) {
            const int j = bj0 + 16 * i;
            cp_async16(dst + (uint32_t)(j * BST + bch * 8) * 2,
                       g_Bh + (size_t)(k0 + jb + j) * BHC + bch * 8);
        }
        if (tid < 64)
            cp_async16(dst + (uint32_t)(tid * BST + 128) * 2,
                       g_Bh + (size_t)(k0 + jb + tid) * BHC + 128);
        CP_COMMIT();
    };

    issueB(0, 0);
    issueB(1, 64);

    int4 av[2][2];
#pragma unroll
    for (int cc = 0; cc < 2; cc++) { av[cc][0] = adjp[cc][0]; av[cc][1] = adjp[cc][1]; }
    uint4 qu = *(const uint4*)(g_Qh + k0 + jq * 8);

    int bst2 = 2;   // stage for B(s+2)
    for (int s = 0; s < 64; s++) {
        const int pb = s & 1;
        __half* Ps = (__half*)(sm + (pb ? PS_B : 0));

        // ---- build P(s): f16x2 + mask ----
#pragma unroll
        for (int cc = 0; cc < 2; cc++) {
            const int row = r0 + 32 * cc;
            const __half2 Rc = R2[cc];
            const int4 a0 = av[cc][0], a1 = av[cc][1];
            uint32_t m0 = (a0.x ? 0xFFFFu : 0u) | (a0.y ? 0xFFFF0000u : 0u);
            uint32_t m1 = (a0.z ? 0xFFFFu : 0u) | (a0.w ? 0xFFFF0000u : 0u);
            uint32_t m2 = (a1.x ? 0xFFFFu : 0u) | (a1.y ? 0xFFFF0000u : 0u);
            uint32_t m3 = (a1.z ? 0xFFFFu : 0u) | (a1.w ? 0xFFFF0000u : 0u);
            __half2 t0 = __hmax2(__hmul2(Rc, *(const __half2*)&qu.x), ONE2);
            __half2 t1 = __hmax2(__hmul2(Rc, *(const __half2*)&qu.y), ONE2);
            __half2 t2 = __hmax2(__hmul2(Rc, *(const __half2*)&qu.z), ONE2);
            __half2 t3 = __hmax2(__hmul2(Rc, *(const __half2*)&qu.w), ONE2);
            uint4 u = make_uint4((*(uint32_t*)&t0) & m0, (*(uint32_t*)&t1) & m1,
                                 (*(uint32_t*)&t2) & m2, (*(uint32_t*)&t3) & m3);
            *(uint4*)&Ps[row * PST + jq * 8] = u;
        }

        // ---- prefetch adj/Qh for tile s+1 ----
        if (s + 1 < 64) {
#pragma unroll
            for (int cc = 0; cc < 2; cc++) {
                av[cc][0] = adjp[cc][(s + 1) * 16];
                av[cc][1] = adjp[cc][(s + 1) * 16 + 1];
            }
            qu = *(const uint4*)(g_Qh + k0 + (s + 1) * 64 + jq * 8);
        }

        CP_WAIT1();            // all but newest group done -> B(s) landed
        __syncthreads();

        // ---- issue B(s+2) (or empty commit to keep group positions) ----
        if (s + 2 < 64) {
            issueB(bst2, (s + 2) * 64);
            if (++bst2 == 3) bst2 = 0;
        } else {
            CP_COMMIT();
        }

        // ---- MMA(s): K=64 in 4 ksteps of 16 ----
        const uint32_t pbo = ps_base + (pb ? PS_B : 0) + a_rel;
        const uint32_t bbo = ps_base + OFF_BS + (s % 3) * BS_B + b_rel;
#pragma unroll
        for (int k = 0; k < 4; k++) {
            const int kk = k * 16;
            uint32_t afr[2][4];
            ldsm_x4(afr[0], pbo + kk * 2);
            ldsm_x4(afr[1], pbo + (16 * PST + kk) * 2);
            uint32_t bfr[2][4];
            ldsm_x4_t(bfr[0], bbo + (kk * BST) * 2);
            ldsm_x4_t(bfr[1], bbo + (kk * BST + 16) * 2);
#pragma unroll
            for (int pr = 0; pr < 2; pr++) {
#pragma unroll
                for (int mt = 0; mt < 2; mt++) {
                    mma_f16(acc[mt][pr * 2], afr[mt], &bfr[pr][0]);
                    mma_f16(acc[mt][pr * 2 + 1], afr[mt], &bfr[pr][2]);
                }
            }
            if (wn == 3) {   // den column (col 128) lives at warp-col base 96+32
                uint32_t bfrD[4];
                ldsm_x4_t(bfrD, bbo + (kk * BST + 32) * 2);
                mma_f16(accD[0], afr[0], &bfrD[0]);
                mma_f16(accD[1], afr[1], &bfrD[0]);
            }
        }
    }

    // ---- writeback ----
    const size_t base = (size_t)kh * NN + row0;
#pragma unroll
    for (int mt = 0; mt < 2; mt++) {
        const int r_lo = wm * 32 + mt * 16 + gr;
#pragma unroll
        for (int nt = 0; nt < 4; nt++) {
            const int col = wn * 32 + nt * 8 + 2 * tg;
            *(float2*)&g_pnum[(base + r_lo) * 128 + col] = make_float2(acc[mt][nt][0], acc[mt][nt][1]);
            *(float2*)&g_pnum[(base + r_lo + 8) * 128 + col] = make_float2(acc[mt][nt][2], acc[mt][nt][3]);
        }
        if (wn == 3 && tg == 0) {
            g_pden[base + r_lo] = accD[mt][0];
            g_pden[base + r_lo + 8] = accD[mt][2];
        }
    }
}

// ---------------------------------------------------------------------------
// Kernel D: finalize  out = elu((n0+n1)/(d0+d1))
// ---------------------------------------------------------------------------
__global__ __launch_bounds__(256) void finalize_kernel(float* __restrict__ out) {
    const int idx = blockIdx.x * 256 + threadIdx.x;
    const int row = idx >> 5, c4 = idx & 31;
    float4 n0 = ((const float4*)g_pnum)[(size_t)row * 32 + c4];
    float4 n1 = ((const float4*)g_pnum)[(size_t)(NN + row) * 32 + c4];
    const float rinv = 1.0f / (g_pden[row] + g_pden[NN + row]);
    float4 o;
    float x;
    x = (n0.x + n1.x) * rinv; o.x = x > 0.f ? x : expm1f(x);
    x = (n0.y + n1.y) * rinv; o.y = x > 0.f ? x : expm1f(x);
    x = (n0.z + n1.z) * rinv; o.z = x > 0.f ? x : expm1f(x);
    x = (n0.w + n1.w) * rinv; o.w = x > 0.f ? x : expm1f(x);
    ((float4*)out)[(size_t)row * 32 + c4] = o;
}

// ---------------------------------------------------------------------------
extern "C" void kernel_launch(void* const* d_in, const int* in_sizes, int n_in,
                              void* d_out, int out_size) {
    const float* h = (const float*)d_in[0];
    const int* adj = (const int*)d_in[1];
    const float* W = (const float*)d_in[2];
    const float* a = (const float*)d_in[3];
    float* out = (float*)d_out;

    cudaFuncSetAttribute(attn_mma_kernel, cudaFuncAttributeMaxDynamicSharedMemorySize,
                         ATTN_SMEM);

    wh_kernel<<<NN / 64, 256>>>(h, W);
    srcdst_kernel<<<NN / 64, 256>>>(a);
    bh_kernel<<<NN * 32 / 256, 256>>>();
    attn_mma_kernel<<<256, 256, ATTN_SMEM>>>(adj);
    finalize_kernel<<<1024, 256>>>(out);
}

// round 14
// speedup vs baseline: 1.0571x; 1.0571x over previous
#include <cuda_runtime.h>
#include <cuda_fp16.h>
#include <stdint.h>
#include <math.h>

#define NN 8192
#define INF_ 256
#define OUTF 128
#define BHC 136     // g_Bh cols: 0-127 = D5*Wh, 128 = D5, 129-135 = 0

// ------------------------------ scratch ------------------------------------
__device__ float g_Wh[NN * OUTF];                 // 4 MB
__device__ __align__(16) __half g_Bh[NN * BHC];   // 2.2 MB
__device__ float g_R[NN];                         // exp(0.8*src)
__device__ __half g_Qh[NN];                       // f16(exp(0.8*dst))
__device__ float g_D5[NN];                        // exp(0.2*dst)
__device__ float g_pnum[2 * NN * OUTF];           // split-K partial numerators
__device__ float g_pden[2 * NN];                  // split-K partial denominators

// ------------------------------ helpers ------------------------------------
__device__ __forceinline__ uint32_t smem_u32(const void* p) {
    return (uint32_t)__cvta_generic_to_shared(p);
}
__device__ __forceinline__ void ldsm_x4(uint32_t* r, uint32_t addr) {
    asm volatile("ldmatrix.sync.aligned.m8n8.x4.shared.b16 {%0,%1,%2,%3}, [%4];"
        : "=r"(r[0]), "=r"(r[1]), "=r"(r[2]), "=r"(r[3]) : "r"(addr));
}
__device__ __forceinline__ void ldsm_x4_t(uint32_t* r, uint32_t addr) {
    asm volatile("ldmatrix.sync.aligned.m8n8.x4.trans.shared.b16 {%0,%1,%2,%3}, [%4];"
        : "=r"(r[0]), "=r"(r[1]), "=r"(r[2]), "=r"(r[3]) : "r"(addr));
}
__device__ __forceinline__ void mma_f16(float* d, const uint32_t* a, const uint32_t* b) {
    asm volatile(
        "mma.sync.aligned.m16n8k16.row.col.f32.f16.f16.f32 "
        "{%0,%1,%2,%3}, {%4,%5,%6,%7}, {%8,%9}, {%0,%1,%2,%3};"
        : "+f"(d[0]), "+f"(d[1]), "+f"(d[2]), "+f"(d[3])
        : "r"(a[0]), "r"(a[1]), "r"(a[2]), "r"(a[3]), "r"(b[0]), "r"(b[1]));
}
__device__ __forceinline__ uint32_t pack_h2(float lo, float hi) {
    __half2 h = __float22half2_rn(make_float2(lo, hi));
    return *(uint32_t*)&h;
}
__device__ __forceinline__ void cp_async16(uint32_t dst, const void* src) {
    asm volatile("cp.async.cg.shared.global [%0], [%1], 16;" :: "r"(dst), "l"(src));
}
#define CP_COMMIT()  asm volatile("cp.async.commit_group;" ::: "memory")
#define CP_WAIT1()   asm volatile("cp.async.wait_group 1;" ::: "memory")

// ---------------------------------------------------------------------------
// Kernel A: Wh = h @ W   (fp32)
// ---------------------------------------------------------------------------
__global__ __launch_bounds__(256) void wh_kernel(const float* __restrict__ h,
                                                 const float* __restrict__ W) {
    __shared__ float hs[64 * 68];
    __shared__ float Ws[64 * 128];
    const int tid = threadIdx.x;
    const int ty = tid >> 4, tx = tid & 15;
    const int rowbase = blockIdx.x * 64;
    float acc[4][8];
#pragma unroll
    for (int i = 0; i < 4; i++)
#pragma unroll
        for (int c = 0; c < 8; c++) acc[i][c] = 0.f;
    const float4* h4 = (const float4*)h;
    const float4* W4 = (const float4*)W;
    for (int kt = 0; kt < INF_; kt += 64) {
        __syncthreads();
#pragma unroll
        for (int s = 0; s < 4; s++) {
            int f4 = tid + s * 256;
            int r = f4 >> 4, c4 = f4 & 15;
            float4 v = h4[(size_t)(rowbase + r) * 64 + (kt >> 2) + c4];
            *(float4*)&hs[r * 68 + c4 * 4] = v;
        }
#pragma unroll
        for (int s = 0; s < 8; s++) {
            int f4 = tid + s * 256;
            ((float4*)Ws)[f4] = W4[kt * 32 + f4];
        }
        __syncthreads();
#pragma unroll 8
        for (int k = 0; k < 64; k++) {
            float hv[4];
#pragma unroll
            for (int i = 0; i < 4; i++) hv[i] = hs[(ty * 4 + i) * 68 + k];
            float4 w0 = *(const float4*)&Ws[k * 128 + tx * 4];
            float4 w1 = *(const float4*)&Ws[k * 128 + 64 + tx * 4];
#pragma unroll
            for (int i = 0; i < 4; i++) {
                acc[i][0] += hv[i] * w0.x; acc[i][1] += hv[i] * w0.y;
                acc[i][2] += hv[i] * w0.z; acc[i][3] += hv[i] * w0.w;
                acc[i][4] += hv[i] * w1.x; acc[i][5] += hv[i] * w1.y;
                acc[i][6] += hv[i] * w1.z; acc[i][7] += hv[i] * w1.w;
            }
        }
    }
#pragma unroll
    for (int i = 0; i < 4; i++) {
        int r = rowbase + ty * 4 + i;
        ((float4*)g_Wh)[(size_t)r * 32 + tx] = make_float4(acc[i][0], acc[i][1], acc[i][2], acc[i][3]);
        ((float4*)g_Wh)[(size_t)r * 32 + 16 + tx] = make_float4(acc[i][4], acc[i][5], acc[i][6], acc[i][7]);
    }
}

// ---------------------------------------------------------------------------
// Kernel B: per-node R = exp(0.8*src), Qh = f16(exp(0.8*dst)), D5 = exp(0.2*dst)
// ---------------------------------------------------------------------------
__global__ __launch_bounds__(256) void srcdst_kernel(const float* __restrict__ a) {
    const int tid = threadIdx.x;
    const int row = blockIdx.x * 64 + (tid >> 2);
    const int q = tid & 3;
    const float4* wh4 = (const float4*)(g_Wh + (size_t)row * 128) + q * 8;
    const float4* a4 = (const float4*)a;
    float s1 = 0.f, s2 = 0.f;
#pragma unroll
    for (int t = 0; t < 8; t++) {
        float4 v = wh4[t];
        float4 b1 = a4[q * 8 + t];
        float4 b2 = a4[32 + q * 8 + t];
        s1 += v.x * b1.x + v.y * b1.y + v.z * b1.z + v.w * b1.w;
        s2 += v.x * b2.x + v.y * b2.y + v.z * b2.z + v.w * b2.w;
    }
    s1 += __shfl_xor_sync(0xffffffffu, s1, 1);
    s1 += __shfl_xor_sync(0xffffffffu, s1, 2);
    s2 += __shfl_xor_sync(0xffffffffu, s2, 1);
    s2 += __shfl_xor_sync(0xffffffffu, s2, 2);
    if (q == 0) {
        g_R[row] = __expf(0.8f * s1);
        g_Qh[row] = __float2half(__expf(0.8f * s2));
        g_D5[row] = __expf(0.2f * s2);
    }
}

// ---------------------------------------------------------------------------
// Kernel B2: Bh[j][0..127] = f16(D5_j*Wh[j][c]); Bh[j][128] = f16(D5_j); rest 0
// ---------------------------------------------------------------------------
__global__ __launch_bounds__(256) void bh_kernel() {
    const int idx = blockIdx.x * 256 + threadIdx.x;   // 0..262143
    const int row = idx >> 5, c4 = idx & 31;
    const float d5 = g_D5[row];
    float4 v = ((const float4*)g_Wh)[(size_t)row * 32 + c4];
    uint2 u = make_uint2(pack_h2(v.x * d5, v.y * d5), pack_h2(v.z * d5, v.w * d5));
    *(uint2*)&g_Bh[(size_t)row * BHC + c4 * 4] = u;
    if (c4 == 0) {
        *(uint2*)&g_Bh[(size_t)row * BHC + 128] = make_uint2(pack_h2(d5, 0.f), 0u);
        *(uint2*)&g_Bh[(size_t)row * BHC + 132] = make_uint2(0u, 0u);
    }
}

// ---------------------------------------------------------------------------
// Kernel C: fused masked-attention GEMM, f16 m16n8k16 + ldmatrix.
// grid = 256 (128 row-blocks of 64 x 2 K-halves), block = 256 (8 warps =
// 2m x 4n; wn==3 also computes the den column 128).
// SHIFTED PIPELINE: per iter  wait+bar -> issueB(s+2) -> build P(s+1) -> MMA(s)
// so P is built one full MMA-phase before its consuming barrier, and adj/Qh
// prefetch has ~2 tile periods of latency cover.
// ---------------------------------------------------------------------------
#define PST 72      // P row stride in halves (144 B, conflict-free)
#define BST 152     // B row stride in halves (304 B, conflict-free)
#define PS_B (64 * PST * 2)     //  9216 B per buffer
#define BS_B (64 * BST * 2)     // 19456 B per buffer
#define OFF_BS (2 * PS_B)
#define ATTN_SMEM (OFF_BS + 3 * BS_B)   // 76800 B

__global__ __launch_bounds__(256, 2) void attn_mma_kernel(const int* __restrict__ adj) {
    extern __shared__ char sm[];

    const int tid = threadIdx.x;
    const int lane = tid & 31, wid = tid >> 5;
    const int rb = blockIdx.x >> 1, kh = blockIdx.x & 1;
    const int row0 = rb * 64, k0 = kh * 4096;

    // ---- P-build roles: rows {r0, r0+32}, j in [jq*8, jq*8+8) ----
    const int r0 = tid >> 3;
    const int jq = tid & 7;
    __half2 R2[2];
    const int4* adjp[2];
#pragma unroll
    for (int cc = 0; cc < 2; cc++) {
        R2[cc] = __float2half2_rn(g_R[row0 + r0 + 32 * cc]);
        adjp[cc] = (const int4*)(adj + (size_t)(row0 + r0 + 32 * cc) * NN + k0) + jq * 2;
    }
    const __half2 ONE2 = __float2half2_rn(1.0f);

    // ---- MMA roles: 2m x 4n ----
    const int wm = wid & 1, wn = wid >> 1;
    const int gr = lane >> 2, tg = lane & 3;
    float acc[2][4][4];
    float accD[2][4];
#pragma unroll
    for (int mt = 0; mt < 2; mt++) {
#pragma unroll
        for (int nt = 0; nt < 4; nt++)
#pragma unroll
            for (int i = 0; i < 4; i++) acc[mt][nt][i] = 0.f;
#pragma unroll
        for (int i = 0; i < 4; i++) accD[mt][i] = 0.f;
    }

    const uint32_t ps_base = smem_u32(sm);
    const uint32_t a_rel = (uint32_t)((wm * 32 + (lane & 15)) * PST + (lane >> 4) * 8) * 2;
    const uint32_t b_rel = (uint32_t)((lane & 15) * BST + wn * 32 + (lane >> 4) * 8) * 2;

    // ---- cp.async B roles ----
    const int bj0 = tid >> 4, bch = tid & 15;
    auto issueB = [&](int st, int jb) {
        const uint32_t dst = ps_base + OFF_BS + st * BS_B;
#pragma unroll
        for (int i = 0; i < 4; i++) {
            const int j = bj0 + 16 * i;
            cp_async16(dst + (uint32_t)(j * BST + bch * 8) * 2,
                       g_Bh + (size_t)(k0 + jb + j) * BHC + bch * 8);
        }
        if (tid < 64)
            cp_async16(dst + (uint32_t)(tid * BST + 128) * 2,
                       g_Bh + (size_t)(k0 + jb + tid) * BHC + 128);
        CP_COMMIT();
    };

    // build P(t) from current av/qu into buffer t&1
    int4 av[2][2];
    uint4 qu;
    auto buildP = [&](int t) {
        __half* Ps = (__half*)(sm + ((t & 1) ? PS_B : 0));
#pragma unroll
        for (int cc = 0; cc < 2; cc++) {
            const int row = r0 + 32 * cc;
            const __half2 Rc = R2[cc];
            const int4 a0 = av[cc][0], a1 = av[cc][1];
            uint32_t m0 = (a0.x ? 0xFFFFu : 0u) | (a0.y ? 0xFFFF0000u : 0u);
            uint32_t m1 = (a0.z ? 0xFFFFu : 0u) | (a0.w ? 0xFFFF0000u : 0u);
            uint32_t m2 = (a1.x ? 0xFFFFu : 0u) | (a1.y ? 0xFFFF0000u : 0u);
            uint32_t m3 = (a1.z ? 0xFFFFu : 0u) | (a1.w ? 0xFFFF0000u : 0u);
            __half2 t0 = __hmax2(__hmul2(Rc, *(const __half2*)&qu.x), ONE2);
            __half2 t1 = __hmax2(__hmul2(Rc, *(const __half2*)&qu.y), ONE2);
            __half2 t2 = __hmax2(__hmul2(Rc, *(const __half2*)&qu.z), ONE2);
            __half2 t3 = __hmax2(__hmul2(Rc, *(const __half2*)&qu.w), ONE2);
            uint4 u = make_uint4((*(uint32_t*)&t0) & m0, (*(uint32_t*)&t1) & m1,
                                 (*(uint32_t*)&t2) & m2, (*(uint32_t*)&t3) & m3);
            *(uint4*)&Ps[row * PST + jq * 8] = u;
        }
    };
    auto loadTile = [&](int t) {
#pragma unroll
        for (int cc = 0; cc < 2; cc++) {
            av[cc][0] = adjp[cc][t * 16];
            av[cc][1] = adjp[cc][t * 16 + 1];
        }
        qu = *(const uint4*)(g_Qh + k0 + t * 64 + jq * 8);
    };

    // ---- prologue ----
    issueB(0, 0);
    issueB(1, 64);
    loadTile(0);
    buildP(0);
    loadTile(1);

    int bst2 = 2;
    for (int s = 0; s < 64; s++) {
        CP_WAIT1();          // B(s) landed (newest group may be pending)
        __syncthreads();     // P(s) [built last iter] + B(s) visible to all

        // ---- issue B(s+2) (empty commit keeps group positions) ----
        if (s + 2 < 64) {
            issueB(bst2, (s + 2) * 64);
            if (++bst2 == 3) bst2 = 0;
        } else {
            CP_COMMIT();
        }

        // ---- build P(s+1) from prefetched regs; then prefetch tile s+2 ----
        if (s + 1 < 64) {
            buildP(s + 1);
            if (s + 2 < 64) loadTile(s + 2);
        }

        // ---- MMA(s): K=64 in 4 ksteps of 16 ----
        const uint32_t pbo = ps_base + ((s & 1) ? PS_B : 0) + a_rel;
        const uint32_t bbo = ps_base + OFF_BS + (s % 3) * BS_B + b_rel;
#pragma unroll
        for (int k = 0; k < 4; k++) {
            const int kk = k * 16;
            uint32_t afr[2][4];
            ldsm_x4(afr[0], pbo + kk * 2);
            ldsm_x4(afr[1], pbo + (16 * PST + kk) * 2);
            uint32_t bfr[2][4];
            ldsm_x4_t(bfr[0], bbo + (kk * BST) * 2);
            ldsm_x4_t(bfr[1], bbo + (kk * BST + 16) * 2);
#pragma unroll
            for (int pr = 0; pr < 2; pr++) {
#pragma unroll
                for (int mt = 0; mt < 2; mt++) {
                    mma_f16(acc[mt][pr * 2], afr[mt], &bfr[pr][0]);
                    mma_f16(acc[mt][pr * 2 + 1], afr[mt], &bfr[pr][2]);
                }
            }
            if (wn == 3) {   // den column (col 128) at warp-col base 96+32
                uint32_t bfrD[4];
                ldsm_x4_t(bfrD, bbo + (kk * BST + 32) * 2);
                mma_f16(accD[0], afr[0], &bfrD[0]);
                mma_f16(accD[1], afr[1], &bfrD[0]);
            }
        }
    }

    // ---- writeback ----
    const size_t base = (size_t)kh * NN + row0;
#pragma unroll
    for (int mt = 0; mt < 2; mt++) {
        const int r_lo = wm * 32 + mt * 16 + gr;
#pragma unroll
        for (int nt = 0; nt < 4; nt++) {
            const int col = wn * 32 + nt * 8 + 2 * tg;
            *(float2*)&g_pnum[(base + r_lo) * 128 + col] = make_float2(acc[mt][nt][0], acc[mt][nt][1]);
            *(float2*)&g_pnum[(base + r_lo + 8) * 128 + col] = make_float2(acc[mt][nt][2], acc[mt][nt][3]);
        }
        if (wn == 3 && tg == 0) {
            g_pden[base + r_lo] = accD[mt][0];
            g_pden[base + r_lo + 8] = accD[mt][2];
        }
    }
}

// ---------------------------------------------------------------------------
// Kernel D: finalize  out = elu((n0+n1)/(d0+d1))
// ---------------------------------------------------------------------------
__global__ __launch_bounds__(256) void finalize_kernel(float* __restrict__ out) {
    const int idx = blockIdx.x * 256 + threadIdx.x;
    const int row = idx >> 5, c4 = idx & 31;
    float4 n0 = ((const float4*)g_pnum)[(size_t)row * 32 + c4];
    float4 n1 = ((const float4*)g_pnum)[(size_t)(NN + row) * 32 + c4];
    const float rinv = 1.0f / (g_pden[row] + g_pden[NN + row]);
    float4 o;
    float x;
    x = (n0.x + n1.x) * rinv; o.x = x > 0.f ? x : expm1f(x);
    x = (n0.y + n1.y) * rinv; o.y = x > 0.f ? x : expm1f(x);
    x = (n0.z + n1.z) * rinv; o.z = x > 0.f ? x : expm1f(x);
    x = (n0.w + n1.w) * rinv; o.w = x > 0.f ? x : expm1f(x);
    ((float4*)out)[(size_t)row * 32 + c4] = o;
}

// ---------------------------------------------------------------------------
extern "C" void kernel_launch(void* const* d_in, const int* in_sizes, int n_in,
                              void* d_out, int out_size) {
    const float* h = (const float*)d_in[0];
    const int* adj = (const int*)d_in[1];
    const float* W = (const float*)d_in[2];
    const float* a = (const float*)d_in[3];
    float* out = (float*)d_out;

    cudaFuncSetAttribute(attn_mma_kernel, cudaFuncAttributeMaxDynamicSharedMemorySize,
                         ATTN_SMEM);

    wh_kernel<<<NN / 64, 256>>>(h, W);
    srcdst_kernel<<<NN / 64, 256>>>(a);
    bh_kernel<<<NN * 32 / 256, 256>>>();
    attn_mma_kernel<<<256, 256, ATTN_SMEM>>>(adj);
    finalize_kernel<<<1024, 256>>>(out);
}